// round 15
// baseline (speedup 1.0000x reference)
#include <cuda_runtime.h>
#include <cuda_fp16.h>
#include <math.h>

#define BATCH   2
#define SEQ     2048
#define DMODEL  2048
#define NHEADS  16
#define DHEAD   128
#define SCALE   0.08838834764831845f   // 1/sqrt(128)

// ---------------------------------------------------------------------------
// Scratch (allocation-free: __device__ globals)
// ---------------------------------------------------------------------------
__device__ __half g_Q [BATCH*NHEADS*SEQ*DHEAD];   // [b][h][s][e] fp16, Q pre-scaled
__device__ __half g_K [BATCH*NHEADS*SEQ*DHEAD];   // [b][h][s][e]
__device__ __half g_Vt[BATCH*NHEADS*DHEAD*SEQ];   // [b][h][e][s]  (transposed)

// fp16 fragment-permuted operand panels (1 word = 2 fp16 along k).
#define SLAB_W  4096
#define PANEL_W (32*SLAB_W)   // 131072 words
__device__ unsigned g_Xp [BATCH*SEQ*DMODEL/2];
__device__ unsigned g_Zp [BATCH*SEQ*DMODEL/2];
__device__ unsigned g_Wqp[NHEADS*DMODEL*DHEAD/2];
__device__ unsigned g_Wkp[NHEADS*DMODEL*DHEAD/2];
__device__ unsigned g_Wvp[NHEADS*DMODEL*DHEAD/2];
__device__ unsigned g_WOp[DMODEL*DMODEL/2];

// ---------------------------------------------------------------------------
// helpers
// ---------------------------------------------------------------------------
__device__ __forceinline__ unsigned ph2(float a, float b) {
    __half2 h = __floats2half2_rn(a, b);
    return *(unsigned*)&h;
}

__device__ __forceinline__ void mma_f16(float* c, const unsigned* a, const unsigned* b) {
    asm volatile(
        "mma.sync.aligned.m16n8k16.row.col.f32.f16.f16.f32 "
        "{%0,%1,%2,%3}, {%4,%5,%6,%7}, {%8,%9}, {%0,%1,%2,%3};\n"
        : "+f"(c[0]), "+f"(c[1]), "+f"(c[2]), "+f"(c[3])
        : "r"(a[0]), "r"(a[1]), "r"(a[2]), "r"(a[3]), "r"(b[0]), "r"(b[1]));
}

__device__ __forceinline__ void cp_async16(void* smem_dst, const void* gsrc) {
    unsigned saddr = (unsigned)__cvta_generic_to_shared(smem_dst);
    asm volatile("cp.async.ca.shared.global [%0], [%1], 16;\n" :: "r"(saddr), "l"(gsrc));
}
#define CP_COMMIT() asm volatile("cp.async.commit_group;\n" ::: "memory")
#define CP_WAIT0()  asm volatile("cp.async.wait_group 0;\n" ::: "memory")
#define CP_WAIT1()  asm volatile("cp.async.wait_group 1;\n" ::: "memory")

// A-frag word index within a 128x64 fp16 slab (k even, 0..63)
__device__ __forceinline__ int afrag16(int m, int k) {
    int reg = ((k & 8) >> 2) | ((m & 8) >> 3);
    return ((((m >> 4) * 4 + (k >> 4)) * 32 + (m & 7) * 4 + ((k & 7) >> 1)) << 2) + reg;
}

// ---------------------------------------------------------------------------
// Prepass: A operand (row-major fp32 [4096][2048]) -> fp16 A-frag panels
// ---------------------------------------------------------------------------
__global__ __launch_bounds__(256) void permute_A16(
    const float* __restrict__ src, unsigned* __restrict__ dst, int nchunks)
{
    int gid = blockIdx.x * blockDim.x + threadIdx.x;
    if (gid >= nchunks) return;
    int c = gid & 1023, slab = (gid >> 10) & 31, mt_g = gid >> 15;
    int lane = c & 31, t = c >> 5;
    int kt = t & 3, mt = t >> 2;
    int m = mt_g * 128 + mt * 16 + (lane >> 2);
    int k = slab * 64 + kt * 16 + 2 * (lane & 3);
    const float* s = src + (size_t)m * DMODEL + k;
    uint4 o;
    o.x = ph2(s[0], s[1]);
    o.y = ph2(s[(size_t)8 * DMODEL], s[(size_t)8 * DMODEL + 1]);
    o.z = ph2(s[8], s[9]);
    o.w = ph2(s[(size_t)8 * DMODEL + 8], s[(size_t)8 * DMODEL + 9]);
    *(uint4*)(dst + (size_t)gid * 4) = o;
}

// ---------------------------------------------------------------------------
// Prepass: B operand -> fp16 B-frag panels.
// ---------------------------------------------------------------------------
__global__ __launch_bounds__(256) void permute_B16(
    const float* __restrict__ src, unsigned* __restrict__ dst,
    size_t mat_stride, int ld, float scl, int nchunks)
{
    int gid = blockIdx.x * blockDim.x + threadIdx.x;
    if (gid >= nchunks) return;
    int c = gid & 1023, slab = (gid >> 10) & 31, mat = gid >> 15;
    int p = c * 2;
    int L = p & 31, t = p >> 5;
    int nt = t & 15, kt = t >> 4;
    int n = nt * 8 + (L >> 2);
    int k = slab * 64 + kt * 16 + 2 * (L & 3);
    const float* s = src + (size_t)mat * mat_stride + n;
    uint4 o;
    o.x = ph2(s[(size_t)k * ld] * scl,        s[(size_t)(k + 1) * ld] * scl);
    o.y = ph2(s[(size_t)(k + 8) * ld] * scl,  s[(size_t)(k + 9) * ld] * scl);
    o.z = ph2(s[(size_t)(k + 2) * ld] * scl,  s[(size_t)(k + 3) * ld] * scl);
    o.w = ph2(s[(size_t)(k + 10) * ld] * scl, s[(size_t)(k + 11) * ld] * scl);
    *(uint4*)(dst + (size_t)gid * 4) = o;
}

// ---------------------------------------------------------------------------
// fp16 GEMM mainloop: block tile 128x128, k-slab 64, 3 stages, single barrier
// per slab, issue 2 slabs ahead into the stage freed last iteration.
// ---------------------------------------------------------------------------
#define GSTAGE_W (2 * SLAB_W)
#define GEMM_SMEM_BYTES (3 * GSTAGE_W * 4)    // 98304

__device__ __forceinline__ void gemm_issue16(
    unsigned* stage, const unsigned* __restrict__ A, const unsigned* __restrict__ B, int tid)
{
    #pragma unroll
    for (int i = 0; i < 4; i++) {
        int c = tid + i * 256;
        cp_async16(stage + c * 4, A + (size_t)c * 4);
        cp_async16(stage + SLAB_W + c * 4, B + (size_t)c * 4);
    }
}

__device__ __forceinline__ void gemm_compute16(
    const unsigned* stage, float c[4][4][4], int warpM, int warpN, int lane)
{
    const uint4* A4 = (const uint4*)stage;
    const uint2* B2 = (const uint2*)(stage + SLAB_W);
    #pragma unroll
    for (int kt = 0; kt < 4; kt++) {
        uint4 a[4]; uint2 b[4];
        #pragma unroll
        for (int mi = 0; mi < 4; mi++)
            a[mi] = A4[((warpM * 4 + mi) * 4 + kt) * 32 + lane];
        #pragma unroll
        for (int ni = 0; ni < 4; ni++)
            b[ni] = B2[(kt * 16 + warpN * 4 + ni) * 32 + lane];
        #pragma unroll
        for (int mi = 0; mi < 4; mi++)
            #pragma unroll
            for (int ni = 0; ni < 4; ni++)
                mma_f16(c[mi][ni], (const unsigned*)&a[mi], (const unsigned*)&b[ni]);
    }
}

// pipelined mainloop shared by both GEMMs
__device__ __forceinline__ void gemm_mainloop16(
    unsigned* smp, const unsigned* __restrict__ Ablk0, const unsigned* __restrict__ Bblk0,
    float c[4][4][4], int tid, int warpM, int warpN, int lane)
{
    gemm_issue16(smp,            Ablk0,          Bblk0,          tid); CP_COMMIT();
    gemm_issue16(smp + GSTAGE_W, Ablk0 + SLAB_W, Bblk0 + SLAB_W, tid); CP_COMMIT();

    int st = 0, wst = 2;
    for (int s = 0; s < 32; s++) {
        CP_WAIT1();          // slab s arrived (issued >=1 full compute iter ago)
        __syncthreads();     // visible to all; all warps done with slab s-1
        if (s + 2 < 32)      // write the stage freed at s-1 (barrier-protected)
            gemm_issue16(smp + wst * GSTAGE_W,
                         Ablk0 + (size_t)(s + 2) * SLAB_W,
                         Bblk0 + (size_t)(s + 2) * SLAB_W, tid);
        CP_COMMIT();
        gemm_compute16(smp + st * GSTAGE_W, c, warpM, warpN, lane);
        st  = (st  == 2) ? 0 : st  + 1;
        wst = (wst == 2) ? 0 : wst + 1;
    }
}

// ---------------------------------------------------------------------------
// Phase 1: QKV projection. grid = (16 heads, 32 m-tiles, 3 {Q,K,V}).
// ---------------------------------------------------------------------------
__global__ __launch_bounds__(256) void qkv_gemm16(
    const float* __restrict__ bq, const float* __restrict__ bk, const float* __restrict__ bv)
{
    extern __shared__ __align__(16) unsigned smp[];

    const unsigned* W; const float* bias; float bscale;
    if (blockIdx.z == 0)      { W = g_Wqp; bias = bq; bscale = SCALE; }
    else if (blockIdx.z == 1) { W = g_Wkp; bias = bk; bscale = 1.f; }
    else                      { W = g_Wvp; bias = bv; bscale = 1.f; }

    const int h   = blockIdx.x;
    const int m0  = blockIdx.y * 128;
    const int tid = threadIdx.x;
    const int warp = tid >> 5, lane = tid & 31;
    const int warpM = warp >> 2, warpN = warp & 3;
    const int lq = lane >> 2, lr = lane & 3;
    const unsigned* Ablk0 = g_Xp + (size_t)(m0 >> 7) * PANEL_W;
    const unsigned* Bblk0 = W + (size_t)h * PANEL_W;

    float c[4][4][4];
    #pragma unroll
    for (int mi = 0; mi < 4; mi++)
        #pragma unroll
        for (int ni = 0; ni < 4; ni++)
            #pragma unroll
            for (int j = 0; j < 4; j++) c[mi][ni][j] = 0.f;

    gemm_mainloop16(smp, Ablk0, Bblk0, c, tid, warpM, warpN, lane);

    #pragma unroll
    for (int mi = 0; mi < 4; mi++) {
        #pragma unroll
        for (int half_ = 0; half_ < 2; half_++) {
            int m = m0 + warpM * 64 + mi * 16 + lq + half_ * 8;
            int b_ = m >> 11, sdx = m & 2047;
            const size_t head = (size_t)(b_ * NHEADS + h);
            #pragma unroll
            for (int ni = 0; ni < 4; ni++) {
                int n = warpN * 32 + ni * 8 + 2 * lr;
                float v0 = c[mi][ni][half_ * 2 + 0] + bias[h * DHEAD + n]     * bscale;
                float v1 = c[mi][ni][half_ * 2 + 1] + bias[h * DHEAD + n + 1] * bscale;
                if (blockIdx.z == 2) {
                    __half* vt = g_Vt + head * DHEAD * SEQ;
                    vt[(size_t)n * SEQ + sdx]       = __float2half_rn(v0);
                    vt[(size_t)(n + 1) * SEQ + sdx] = __float2half_rn(v1);
                } else {
                    __half* orow = (blockIdx.z == 0 ? g_Q : g_K)
                                   + (head * SEQ + sdx) * DHEAD;
                    *(unsigned*)(orow + n) = ph2(v0, v1);
                }
            }
        }
    }
}

// ---------------------------------------------------------------------------
// Phase 2: causal flash attention, register-resident P, double-buffered K/V.
// q-tile 128, kv-tile 64, 256 threads = 8 warps; 1 barrier per kv-tile.
// grid = (8 pair-slots, B*H); CTA runs q-tiles {15-i, i} (34 kv-tiles each).
// smem: Qs [128][68] | buf0{Ks[64][68], Vs[128][36]} | buf1{...}
// ---------------------------------------------------------------------------
#define AQ   0
#define AKV0 (128*68)                      // 8704
#define AKV1 (AKV0 + 64*68 + 128*36)       // 17664
#define ATT_SMEM_W (AKV1 + 64*68 + 128*36) // 26624 words
#define ATT_SMEM_BYTES (ATT_SMEM_W * 4)    // 106496

__global__ __launch_bounds__(256, 2) void attn16()
{
    extern __shared__ __align__(16) unsigned smu[];
    unsigned* Qs = smu + AQ;   // [128][68] words (64 used/row)

    const int tid = threadIdx.x;
    const int warp = tid >> 5, lane = tid & 31;
    const int lq = lane >> 2, lr = lane & 3;
    const int bh = blockIdx.y;
    const int b  = bh >> 4, h = bh & 15;
    const int r_loc = warp * 16 + lq;    // 0..127

    const __half* Qg  = g_Q  + (size_t)(b * NHEADS + h) * SEQ * DHEAD;
    const __half* Kg  = g_K  + (size_t)(b * NHEADS + h) * SEQ * DHEAD;
    const __half* Vtg = g_Vt + (size_t)(b * NHEADS + h) * DHEAD * SEQ;

    for (int run = 0; run < 2; run++) {
        const int qt = (run == 0) ? (15 - (int)blockIdx.x) : (int)blockIdx.x;
        const int q0 = qt * 128;
        const int ntiles = 2 * qt + 2;

        __syncthreads();   // protect Qs / KV buffers from prior run's readers

        // stage Q (128 rows x 64 words)
        #pragma unroll
        for (int i = 0; i < 8; i++) {
            int idx = tid + i * 256;
            int row = idx >> 4, cw = (idx & 15) * 4;
            cp_async16(Qs + row * 68 + cw, Qg + (size_t)(q0 + row) * DHEAD + cw * 2);
        }
        CP_COMMIT();
        // stage KV(0) into buf0
        {
            unsigned* Ks0 = smu + AKV0;
            unsigned* Vs0 = smu + AKV0 + 64 * 68;
            #pragma unroll
            for (int i = 0; i < 4; i++) {
                int idx = tid + i * 256;
                int row = idx >> 4, cw = (idx & 15) * 4;
                cp_async16(Ks0 + row * 68 + cw, Kg + (size_t)row * DHEAD + cw * 2);
            }
            #pragma unroll
            for (int i = 0; i < 4; i++) {
                int idx = tid + i * 256;
                int row = idx >> 3, cw = (idx & 7) * 4;
                cp_async16(Vs0 + row * 36 + cw, Vtg + (size_t)row * SEQ + cw * 2);
            }
        }
        CP_COMMIT();

        float o[16][4];
        #pragma unroll
        for (int ni = 0; ni < 16; ni++)
            #pragma unroll
            for (int j = 0; j < 4; j++) o[ni][j] = 0.f;
        float m0v = -INFINITY, m1v = -INFINITY, l0 = 0.f, l1 = 0.f;

        for (int kt2 = 0; kt2 < ntiles; kt2++) {
            CP_WAIT0();        // KV(kt2) (and Q on kt2==0) arrived — issued a full tile ago
            __syncthreads();   // visible; all warps done with buf[(kt2-1)&1]

            // issue KV(kt2+1) into the other buffer (freed at kt2-1)
            if (kt2 + 1 < ntiles) {
                unsigned* Ksn = smu + ((kt2 + 1) & 1 ? AKV1 : AKV0);
                unsigned* Vsn = Ksn + 64 * 68;
                const int kn = (kt2 + 1) * 64;
                #pragma unroll
                for (int i = 0; i < 4; i++) {
                    int idx = tid + i * 256;
                    int row = idx >> 4, cw = (idx & 15) * 4;
                    cp_async16(Ksn + row * 68 + cw, Kg + (size_t)(kn + row) * DHEAD + cw * 2);
                }
                #pragma unroll
                for (int i = 0; i < 4; i++) {
                    int idx = tid + i * 256;
                    int row = idx >> 3, cw = (idx & 7) * 4;
                    cp_async16(Vsn + row * 36 + cw, Vtg + (size_t)row * SEQ + kn + cw * 2);
                }
            }
            CP_COMMIT();

            const unsigned* Ks = smu + (kt2 & 1 ? AKV1 : AKV0);
            const unsigned* Vs = Ks + 64 * 68;
            const int k0t = kt2 * 64;

            // S = Q K^T : warp 16 x 64 (8 n-tiles), k=128 -> 8 k16 steps
            float s[8][4];
            #pragma unroll
            for (int ni = 0; ni < 8; ni++)
                #pragma unroll
                for (int j = 0; j < 4; j++) s[ni][j] = 0.f;

            #pragma unroll
            for (int kt = 0; kt < 8; kt++) {
                unsigned aq[4];
                const int kw = kt * 8 + lr;
                aq[0] = Qs[r_loc * 68 + kw];        aq[1] = Qs[(r_loc + 8) * 68 + kw];
                aq[2] = Qs[r_loc * 68 + kw + 4];    aq[3] = Qs[(r_loc + 8) * 68 + kw + 4];
                #pragma unroll
                for (int ni = 0; ni < 8; ni++) {
                    unsigned bb[2];
                    int nb = ni * 8 + lq;
                    bb[0] = Ks[nb * 68 + kw];
                    bb[1] = Ks[nb * 68 + kw + 4];
                    mma_f16(s[ni], aq, bb);
                }
            }

            // causal mask + warp-local row max (quad shuffle)
            const int r0g = q0 + r_loc, r1g = r0g + 8;
            float mx0 = -1e30f, mx1 = -1e30f;
            #pragma unroll
            for (int ni = 0; ni < 8; ni++) {
                int cb = k0t + ni * 8 + 2 * lr;
                if (cb     > r0g) s[ni][0] = -1e30f;
                if (cb + 1 > r0g) s[ni][1] = -1e30f;
                if (cb     > r1g) s[ni][2] = -1e30f;
                if (cb + 1 > r1g) s[ni][3] = -1e30f;
                mx0 = fmaxf(mx0, fmaxf(s[ni][0], s[ni][1]));
                mx1 = fmaxf(mx1, fmaxf(s[ni][2], s[ni][3]));
            }
            mx0 = fmaxf(mx0, __shfl_xor_sync(0xffffffffu, mx0, 1));
            mx0 = fmaxf(mx0, __shfl_xor_sync(0xffffffffu, mx0, 2));
            mx1 = fmaxf(mx1, __shfl_xor_sync(0xffffffffu, mx1, 1));
            mx1 = fmaxf(mx1, __shfl_xor_sync(0xffffffffu, mx1, 2));

            float mn0 = fmaxf(m0v, mx0), mn1 = fmaxf(m1v, mx1);
            float ef0 = __expf(m0v - mn0), ef1 = __expf(m1v - mn1);
            m0v = mn0; m1v = mn1;

            // exp + row sum + pack P (register-resident)
            float sum0 = 0.f, sum1 = 0.f;
            unsigned p01[8], p23[8];
            #pragma unroll
            for (int ni = 0; ni < 8; ni++) {
                float e0 = __expf(s[ni][0] - mn0);
                float e1 = __expf(s[ni][1] - mn0);
                float e2 = __expf(s[ni][2] - mn1);
                float e3 = __expf(s[ni][3] - mn1);
                sum0 += e0 + e1; sum1 += e2 + e3;
                p01[ni] = ph2(e0, e1);
                p23[ni] = ph2(e2, e3);
            }
            sum0 += __shfl_xor_sync(0xffffffffu, sum0, 1);
            sum0 += __shfl_xor_sync(0xffffffffu, sum0, 2);
            sum1 += __shfl_xor_sync(0xffffffffu, sum1, 1);
            sum1 += __shfl_xor_sync(0xffffffffu, sum1, 2);
            l0 = l0 * ef0 + sum0;
            l1 = l1 * ef1 + sum1;

            // rescale O
            #pragma unroll
            for (int ni = 0; ni < 16; ni++) {
                o[ni][0] *= ef0; o[ni][1] *= ef0;
                o[ni][2] *= ef1; o[ni][3] *= ef1;
            }

            // O += P @ V : warp 16 x 128 (16 n-tiles), k=64 -> 4 k16 steps
            #pragma unroll
            for (int t = 0; t < 4; t++) {
                unsigned ap[4] = { p01[2*t], p23[2*t], p01[2*t + 1], p23[2*t + 1] };
                const int kw = t * 8 + lr;
                #pragma unroll
                for (int ni = 0; ni < 16; ni++) {
                    unsigned bb[2];
                    int nb = ni * 8 + lq;
                    bb[0] = Vs[nb * 36 + kw];
                    bb[1] = Vs[nb * 36 + kw + 4];
                    mma_f16(o[ni], ap, bb);
                }
            }
        }

        // normalize + scatter-write Z into fp16 A-frag panels
        float inv0 = 1.f / l0, inv1 = 1.f / l1;
        const int mglob0 = b * SEQ + q0;     // 128-aligned
        unsigned* Zt = g_Zp + (size_t)(mglob0 >> 7) * PANEL_W;
        const int mrow = r_loc;
        #pragma unroll
        for (int ni = 0; ni < 16; ni++) {
            int e = ni * 8 + 2 * lr;
            int kg = h * DHEAD + e;
            unsigned* Zs = Zt + (size_t)(kg >> 6) * SLAB_W;
            int kl = kg & 63;
            Zs[afrag16(mrow,     kl)] = ph2(o[ni][0] * inv0, o[ni][1] * inv0);
            Zs[afrag16(mrow + 8, kl)] = ph2(o[ni][2] * inv1, o[ni][3] * inv1);
        }
    }
}

// ---------------------------------------------------------------------------
// Phase 3: output projection. grid = (16 n-tiles, 32 m-tiles)
// ---------------------------------------------------------------------------
__global__ __launch_bounds__(256) void out_gemm16(
    const float* __restrict__ bO, float* __restrict__ out)
{
    extern __shared__ __align__(16) unsigned smp[];

    const int n0  = blockIdx.x * 128;
    const int m0  = blockIdx.y * 128;
    const int tid = threadIdx.x;
    const int warp = tid >> 5, lane = tid & 31;
    const int warpM = warp >> 2, warpN = warp & 3;
    const int lq = lane >> 2, lr = lane & 3;

    const unsigned* Ablk0 = g_Zp + (size_t)(m0 >> 7) * PANEL_W;
    const unsigned* Bblk0 = g_WOp + (size_t)(n0 >> 7) * PANEL_W;

    float c[4][4][4];
    #pragma unroll
    for (int mi = 0; mi < 4; mi++)
        #pragma unroll
        for (int ni = 0; ni < 4; ni++)
            #pragma unroll
            for (int j = 0; j < 4; j++) c[mi][ni][j] = 0.f;

    gemm_mainloop16(smp, Ablk0, Bblk0, c, tid, warpM, warpN, lane);

    #pragma unroll
    for (int mi = 0; mi < 4; mi++) {
        #pragma unroll
        for (int half_ = 0; half_ < 2; half_++) {
            int m = m0 + warpM * 64 + mi * 16 + lq + half_ * 8;
            float* orow = out + (size_t)m * DMODEL + n0;
            #pragma unroll
            for (int ni = 0; ni < 4; ni++) {
                int n = warpN * 32 + ni * 8 + 2 * lr;
                float2 r;
                r.x = c[mi][ni][half_ * 2 + 0] + bO[n0 + n];
                r.y = c[mi][ni][half_ * 2 + 1] + bO[n0 + n + 1];
                *(float2*)(orow + n) = r;
            }
        }
    }
}

// ---------------------------------------------------------------------------
extern "C" void kernel_launch(void* const* d_in, const int* in_sizes, int n_in,
                              void* d_out, int out_size)
{
    const float* x  = (const float*)d_in[0];
    const float* Wq = (const float*)d_in[1];
    const float* Wk = (const float*)d_in[2];
    const float* Wv = (const float*)d_in[3];
    const float* Wo = (const float*)d_in[4];
    const float* bq = (const float*)d_in[5];
    const float* bk = (const float*)d_in[6];
    const float* bv = (const float*)d_in[7];
    const float* bo = (const float*)d_in[8];
    float* out = (float*)d_out;

    unsigned *pXp, *pWqp, *pWkp, *pWvp, *pWOp;
    cudaGetSymbolAddress((void**)&pXp,  g_Xp);
    cudaGetSymbolAddress((void**)&pWqp, g_Wqp);
    cudaGetSymbolAddress((void**)&pWkp, g_Wkp);
    cudaGetSymbolAddress((void**)&pWvp, g_Wvp);
    cudaGetSymbolAddress((void**)&pWOp, g_WOp);

    const int NXC = 32 * 32 * 1024;
    const int NWC = 16 * 32 * 1024;
    permute_A16<<<(NXC + 255) / 256, 256>>>(x, pXp, NXC);
    permute_B16<<<(NWC + 255) / 256, 256>>>(Wq, pWqp, (size_t)DMODEL * DHEAD, DHEAD, SCALE, NWC);
    permute_B16<<<(NWC + 255) / 256, 256>>>(Wk, pWkp, (size_t)DMODEL * DHEAD, DHEAD, 1.f, NWC);
    permute_B16<<<(NWC + 255) / 256, 256>>>(Wv, pWvp, (size_t)DMODEL * DHEAD, DHEAD, 1.f, NWC);
    permute_B16<<<(NWC + 255) / 256, 256>>>(Wo, pWOp, (size_t)128, DMODEL, 1.f, NWC);

    dim3 blk(256);

    cudaFuncSetAttribute(qkv_gemm16, cudaFuncAttributeMaxDynamicSharedMemorySize, GEMM_SMEM_BYTES);
    qkv_gemm16<<<dim3(16, 32, 3), blk, GEMM_SMEM_BYTES>>>(bq, bk, bv);

    cudaFuncSetAttribute(attn16, cudaFuncAttributeMaxDynamicSharedMemorySize, ATT_SMEM_BYTES);
    attn16<<<dim3(8, 32), blk, ATT_SMEM_BYTES>>>();

    cudaFuncSetAttribute(out_gemm16, cudaFuncAttributeMaxDynamicSharedMemorySize, GEMM_SMEM_BYTES);
    out_gemm16<<<dim3(16, 32), blk, GEMM_SMEM_BYTES>>>(bo, out);
}

// round 17
// speedup vs baseline: 1.0722x; 1.0722x over previous
#include <cuda_runtime.h>
#include <cuda_fp16.h>
#include <math.h>

#define BATCH   2
#define SEQ     2048
#define DMODEL  2048
#define NHEADS  16
#define DHEAD   128
#define SCALE   0.08838834764831845f   // 1/sqrt(128)

// ---------------------------------------------------------------------------
// Scratch (allocation-free: __device__ globals)
// ---------------------------------------------------------------------------
__device__ __half g_Q [BATCH*NHEADS*SEQ*DHEAD];   // [b][h][s][e] fp16, Q pre-scaled
__device__ __half g_K [BATCH*NHEADS*SEQ*DHEAD];   // [b][h][s][e]
__device__ __half g_Vt[BATCH*NHEADS*DHEAD*SEQ];   // [b][h][e][s]  (transposed)

// fp16 fragment-permuted operand panels (1 word = 2 fp16 along k).
#define SLAB_W  4096
#define PANEL_W (32*SLAB_W)   // 131072 words
__device__ unsigned g_Xp [BATCH*SEQ*DMODEL/2];
__device__ unsigned g_Zp [BATCH*SEQ*DMODEL/2];
__device__ unsigned g_Wqp[NHEADS*DMODEL*DHEAD/2];
__device__ unsigned g_Wkp[NHEADS*DMODEL*DHEAD/2];
__device__ unsigned g_Wvp[NHEADS*DMODEL*DHEAD/2];
__device__ unsigned g_WOp[DMODEL*DMODEL/2];

// ---------------------------------------------------------------------------
// helpers
// ---------------------------------------------------------------------------
__device__ __forceinline__ unsigned ph2(float a, float b) {
    __half2 h = __floats2half2_rn(a, b);
    return *(unsigned*)&h;
}

__device__ __forceinline__ void mma_f16(float* c, const unsigned* a, const unsigned* b) {
    asm volatile(
        "mma.sync.aligned.m16n8k16.row.col.f32.f16.f16.f32 "
        "{%0,%1,%2,%3}, {%4,%5,%6,%7}, {%8,%9}, {%0,%1,%2,%3};\n"
        : "+f"(c[0]), "+f"(c[1]), "+f"(c[2]), "+f"(c[3])
        : "r"(a[0]), "r"(a[1]), "r"(a[2]), "r"(a[3]), "r"(b[0]), "r"(b[1]));
}

__device__ __forceinline__ void cp_async16(void* smem_dst, const void* gsrc) {
    unsigned saddr = (unsigned)__cvta_generic_to_shared(smem_dst);
    asm volatile("cp.async.ca.shared.global [%0], [%1], 16;\n" :: "r"(saddr), "l"(gsrc));
}
#define CP_COMMIT() asm volatile("cp.async.commit_group;\n" ::: "memory")
#define CP_WAIT0()  asm volatile("cp.async.wait_group 0;\n" ::: "memory")
#define CP_WAIT1()  asm volatile("cp.async.wait_group 1;\n" ::: "memory")

// A-frag word index within a 128x64 fp16 slab (k even, 0..63)
__device__ __forceinline__ int afrag16(int m, int k) {
    int reg = ((k & 8) >> 2) | ((m & 8) >> 3);
    return ((((m >> 4) * 4 + (k >> 4)) * 32 + (m & 7) * 4 + ((k & 7) >> 1)) << 2) + reg;
}

// ---------------------------------------------------------------------------
// Prepass: A operand (row-major fp32 [4096][2048]) -> fp16 A-frag panels
// ---------------------------------------------------------------------------
__global__ __launch_bounds__(256) void permute_A16(
    const float* __restrict__ src, unsigned* __restrict__ dst, int nchunks)
{
    int gid = blockIdx.x * blockDim.x + threadIdx.x;
    if (gid >= nchunks) return;
    int c = gid & 1023, slab = (gid >> 10) & 31, mt_g = gid >> 15;
    int lane = c & 31, t = c >> 5;
    int kt = t & 3, mt = t >> 2;
    int m = mt_g * 128 + mt * 16 + (lane >> 2);
    int k = slab * 64 + kt * 16 + 2 * (lane & 3);
    const float* s = src + (size_t)m * DMODEL + k;
    uint4 o;
    o.x = ph2(s[0], s[1]);
    o.y = ph2(s[(size_t)8 * DMODEL], s[(size_t)8 * DMODEL + 1]);
    o.z = ph2(s[8], s[9]);
    o.w = ph2(s[(size_t)8 * DMODEL + 8], s[(size_t)8 * DMODEL + 9]);
    *(uint4*)(dst + (size_t)gid * 4) = o;
}

// ---------------------------------------------------------------------------
// Prepass: ALL FOUR B operands in one launch (blockIdx.y selects weight).
// y=0..2: QKV weights [h][k][n] ld=128; y=3: WO [k][n] ld=2048.
// ---------------------------------------------------------------------------
__global__ __launch_bounds__(256) void permute_B16_all(
    const float* __restrict__ Wq, const float* __restrict__ Wk,
    const float* __restrict__ Wv, const float* __restrict__ Wo,
    unsigned* __restrict__ dq, unsigned* __restrict__ dk,
    unsigned* __restrict__ dv, unsigned* __restrict__ dwo, int nchunks)
{
    int gid = blockIdx.x * blockDim.x + threadIdx.x;
    if (gid >= nchunks) return;
    const int which = blockIdx.y;
    const float* src; unsigned* dst; size_t mat_stride; int ld; float scl;
    if (which == 0)      { src = Wq; dst = dq;  mat_stride = (size_t)DMODEL*DHEAD; ld = DHEAD;  scl = SCALE; }
    else if (which == 1) { src = Wk; dst = dk;  mat_stride = (size_t)DMODEL*DHEAD; ld = DHEAD;  scl = 1.f; }
    else if (which == 2) { src = Wv; dst = dv;  mat_stride = (size_t)DMODEL*DHEAD; ld = DHEAD;  scl = 1.f; }
    else                 { src = Wo; dst = dwo; mat_stride = (size_t)128;          ld = DMODEL; scl = 1.f; }

    int c = gid & 1023, slab = (gid >> 10) & 31, mat = gid >> 15;
    int p = c * 2;
    int L = p & 31, t = p >> 5;
    int nt = t & 15, kt = t >> 4;
    int n = nt * 8 + (L >> 2);
    int k = slab * 64 + kt * 16 + 2 * (L & 3);
    const float* s = src + (size_t)mat * mat_stride + n;
    uint4 o;
    o.x = ph2(s[(size_t)k * ld] * scl,        s[(size_t)(k + 1) * ld] * scl);
    o.y = ph2(s[(size_t)(k + 8) * ld] * scl,  s[(size_t)(k + 9) * ld] * scl);
    o.z = ph2(s[(size_t)(k + 2) * ld] * scl,  s[(size_t)(k + 3) * ld] * scl);
    o.w = ph2(s[(size_t)(k + 10) * ld] * scl, s[(size_t)(k + 11) * ld] * scl);
    *(uint4*)(dst + (size_t)gid * 4) = o;
}

// ---------------------------------------------------------------------------
// fp16 GEMM: block tile 128x128, 4 warps (64x64 warp tiles), 128 threads,
// k-slab 64, 3-stage pipelined cp.async, 1 barrier per slab.
// ---------------------------------------------------------------------------
#define GSTAGE_W (2 * SLAB_W)
#define GEMM_SMEM_BYTES (3 * GSTAGE_W * 4)    // 98304

__device__ __forceinline__ void gemm_issue16(
    unsigned* stage, const unsigned* __restrict__ A, const unsigned* __restrict__ B, int tid)
{
    #pragma unroll
    for (int i = 0; i < 8; i++) {
        int c = tid + i * 128;
        cp_async16(stage + c * 4, A + (size_t)c * 4);
        cp_async16(stage + SLAB_W + c * 4, B + (size_t)c * 4);
    }
}

__device__ __forceinline__ void gemm_compute64(
    const unsigned* stage, float c[4][8][4], int warpM, int warpN, int lane)
{
    const uint4* A4 = (const uint4*)stage;
    const uint2* B2 = (const uint2*)(stage + SLAB_W);
    #pragma unroll
    for (int kt = 0; kt < 4; kt++) {
        uint4 a[4]; uint2 b[8];
        #pragma unroll
        for (int mi = 0; mi < 4; mi++)
            a[mi] = A4[((warpM * 4 + mi) * 4 + kt) * 32 + lane];
        #pragma unroll
        for (int ni = 0; ni < 8; ni++)
            b[ni] = B2[(kt * 16 + warpN * 8 + ni) * 32 + lane];
        #pragma unroll
        for (int mi = 0; mi < 4; mi++)
            #pragma unroll
            for (int ni = 0; ni < 8; ni++)
                mma_f16(c[mi][ni], (const unsigned*)&a[mi], (const unsigned*)&b[ni]);
    }
}

__device__ __forceinline__ void gemm_mainloop64(
    unsigned* smp, const unsigned* __restrict__ Ablk0, const unsigned* __restrict__ Bblk0,
    float c[4][8][4], int tid, int warpM, int warpN, int lane)
{
    gemm_issue16(smp,            Ablk0,          Bblk0,          tid); CP_COMMIT();
    gemm_issue16(smp + GSTAGE_W, Ablk0 + SLAB_W, Bblk0 + SLAB_W, tid); CP_COMMIT();

    int st = 0, wst = 2;
    for (int s = 0; s < 32; s++) {
        CP_WAIT1();
        __syncthreads();
        if (s + 2 < 32)
            gemm_issue16(smp + wst * GSTAGE_W,
                         Ablk0 + (size_t)(s + 2) * SLAB_W,
                         Bblk0 + (size_t)(s + 2) * SLAB_W, tid);
        CP_COMMIT();
        gemm_compute64(smp + st * GSTAGE_W, c, warpM, warpN, lane);
        st  = (st  == 2) ? 0 : st  + 1;
        wst = (wst == 2) ? 0 : wst + 1;
    }
}

// ---------------------------------------------------------------------------
// Phase 1: QKV projection. grid = (16 heads, 32 m-tiles, 3 {Q,K,V}), 128 thr.
// ---------------------------------------------------------------------------
__global__ __launch_bounds__(128) void qkv_gemm16(
    const float* __restrict__ bq, const float* __restrict__ bk, const float* __restrict__ bv)
{
    extern __shared__ __align__(16) unsigned smp[];

    const unsigned* W; const float* bias; float bscale;
    if (blockIdx.z == 0)      { W = g_Wqp; bias = bq; bscale = SCALE; }
    else if (blockIdx.z == 1) { W = g_Wkp; bias = bk; bscale = 1.f; }
    else                      { W = g_Wvp; bias = bv; bscale = 1.f; }

    const int h   = blockIdx.x;
    const int m0  = blockIdx.y * 128;
    const int tid = threadIdx.x;
    const int warp = tid >> 5, lane = tid & 31;
    const int warpM = warp >> 1, warpN = warp & 1;
    const int lq = lane >> 2, lr = lane & 3;
    const unsigned* Ablk0 = g_Xp + (size_t)(m0 >> 7) * PANEL_W;
    const unsigned* Bblk0 = W + (size_t)h * PANEL_W;

    float c[4][8][4];
    #pragma unroll
    for (int mi = 0; mi < 4; mi++)
        #pragma unroll
        for (int ni = 0; ni < 8; ni++)
            #pragma unroll
            for (int j = 0; j < 4; j++) c[mi][ni][j] = 0.f;

    gemm_mainloop64(smp, Ablk0, Bblk0, c, tid, warpM, warpN, lane);

    #pragma unroll
    for (int mi = 0; mi < 4; mi++) {
        #pragma unroll
        for (int half_ = 0; half_ < 2; half_++) {
            int m = m0 + warpM * 64 + mi * 16 + lq + half_ * 8;
            int b_ = m >> 11, sdx = m & 2047;
            const size_t head = (size_t)(b_ * NHEADS + h);
            #pragma unroll
            for (int ni = 0; ni < 8; ni++) {
                int n = warpN * 64 + ni * 8 + 2 * lr;
                float v0 = c[mi][ni][half_ * 2 + 0] + bias[h * DHEAD + n]     * bscale;
                float v1 = c[mi][ni][half_ * 2 + 1] + bias[h * DHEAD + n + 1] * bscale;
                if (blockIdx.z == 2) {
                    __half* vt = g_Vt + head * DHEAD * SEQ;
                    vt[(size_t)n * SEQ + sdx]       = __float2half_rn(v0);
                    vt[(size_t)(n + 1) * SEQ + sdx] = __float2half_rn(v1);
                } else {
                    __half* orow = (blockIdx.z == 0 ? g_Q : g_K)
                                   + (head * SEQ + sdx) * DHEAD;
                    *(unsigned*)(orow + n) = ph2(v0, v1);
                }
            }
        }
    }
}

// ---------------------------------------------------------------------------
// Phase 2: causal flash attention, register-resident P, double-buffered K/V.
// q-tile 128, kv-tile 64, 256 threads = 8 warps; 1 barrier per kv-tile.
// grid = (8 pair-slots, B*H); CTA runs q-tiles {15-i, i} (34 kv-tiles each).
// Interior tiles skip the causal-mask arithmetic entirely.
// ---------------------------------------------------------------------------
#define AQ   0
#define AKV0 (128*68)                      // 8704
#define AKV1 (AKV0 + 64*68 + 128*36)       // 17664
#define ATT_SMEM_W (AKV1 + 64*68 + 128*36) // 26624 words
#define ATT_SMEM_BYTES (ATT_SMEM_W * 4)    // 106496

__global__ __launch_bounds__(256, 2) void attn16()
{
    extern __shared__ __align__(16) unsigned smu[];
    unsigned* Qs = smu + AQ;   // [128][68] words (64 used/row)

    const int tid = threadIdx.x;
    const int warp = tid >> 5, lane = tid & 31;
    const int lq = lane >> 2, lr = lane & 3;
    const int bh = blockIdx.y;
    const int b  = bh >> 4, h = bh & 15;
    const int r_loc = warp * 16 + lq;    // 0..127

    const __half* Qg  = g_Q  + (size_t)(b * NHEADS + h) * SEQ * DHEAD;
    const __half* Kg  = g_K  + (size_t)(b * NHEADS + h) * SEQ * DHEAD;
    const __half* Vtg = g_Vt + (size_t)(b * NHEADS + h) * DHEAD * SEQ;

    for (int run = 0; run < 2; run++) {
        const int qt = (run == 0) ? (15 - (int)blockIdx.x) : (int)blockIdx.x;
        const int q0 = qt * 128;
        const int ntiles = 2 * qt + 2;

        __syncthreads();   // protect Qs / KV buffers from prior run's readers

        #pragma unroll
        for (int i = 0; i < 8; i++) {
            int idx = tid + i * 256;
            int row = idx >> 4, cw = (idx & 15) * 4;
            cp_async16(Qs + row * 68 + cw, Qg + (size_t)(q0 + row) * DHEAD + cw * 2);
        }
        CP_COMMIT();
        {
            unsigned* Ks0 = smu + AKV0;
            unsigned* Vs0 = smu + AKV0 + 64 * 68;
            #pragma unroll
            for (int i = 0; i < 4; i++) {
                int idx = tid + i * 256;
                int row = idx >> 4, cw = (idx & 15) * 4;
                cp_async16(Ks0 + row * 68 + cw, Kg + (size_t)row * DHEAD + cw * 2);
            }
            #pragma unroll
            for (int i = 0; i < 4; i++) {
                int idx = tid + i * 256;
                int row = idx >> 3, cw = (idx & 7) * 4;
                cp_async16(Vs0 + row * 36 + cw, Vtg + (size_t)row * SEQ + cw * 2);
            }
        }
        CP_COMMIT();

        float o[16][4];
        #pragma unroll
        for (int ni = 0; ni < 16; ni++)
            #pragma unroll
            for (int j = 0; j < 4; j++) o[ni][j] = 0.f;
        float m0v = -INFINITY, m1v = -INFINITY, l0 = 0.f, l1 = 0.f;

        for (int kt2 = 0; kt2 < ntiles; kt2++) {
            CP_WAIT0();
            __syncthreads();

            if (kt2 + 1 < ntiles) {
                unsigned* Ksn = smu + ((kt2 + 1) & 1 ? AKV1 : AKV0);
                unsigned* Vsn = Ksn + 64 * 68;
                const int kn = (kt2 + 1) * 64;
                #pragma unroll
                for (int i = 0; i < 4; i++) {
                    int idx = tid + i * 256;
                    int row = idx >> 4, cw = (idx & 15) * 4;
                    cp_async16(Ksn + row * 68 + cw, Kg + (size_t)(kn + row) * DHEAD + cw * 2);
                }
                #pragma unroll
                for (int i = 0; i < 4; i++) {
                    int idx = tid + i * 256;
                    int row = idx >> 3, cw = (idx & 7) * 4;
                    cp_async16(Vsn + row * 36 + cw, Vtg + (size_t)row * SEQ + kn + cw * 2);
                }
            }
            CP_COMMIT();

            const unsigned* Ks = smu + (kt2 & 1 ? AKV1 : AKV0);
            const unsigned* Vs = Ks + 64 * 68;
            const int k0t = kt2 * 64;

            // S = Q K^T : warp 16 x 64 (8 n-tiles), k=128
            float s[8][4];
            #pragma unroll
            for (int ni = 0; ni < 8; ni++)
                #pragma unroll
                for (int j = 0; j < 4; j++) s[ni][j] = 0.f;

            #pragma unroll
            for (int kt = 0; kt < 8; kt++) {
                unsigned aq[4];
                const int kw = kt * 8 + lr;
                aq[0] = Qs[r_loc * 68 + kw];        aq[1] = Qs[(r_loc + 8) * 68 + kw];
                aq[2] = Qs[r_loc * 68 + kw + 4];    aq[3] = Qs[(r_loc + 8) * 68 + kw + 4];
                #pragma unroll
                for (int ni = 0; ni < 8; ni++) {
                    unsigned bb[2];
                    int nb = ni * 8 + lq;
                    bb[0] = Ks[nb * 68 + kw];
                    bb[1] = Ks[nb * 68 + kw + 4];
                    mma_f16(s[ni], aq, bb);
                }
            }

            // causal mask — only where the tile can cross the diagonal
            const int r0g = q0 + r_loc, r1g = r0g + 8;
            if (k0t + 63 > q0 + warp * 16) {
                #pragma unroll
                for (int ni = 0; ni < 8; ni++) {
                    int cb = k0t + ni * 8 + 2 * lr;
                    if (cb     > r0g) s[ni][0] = -1e30f;
                    if (cb + 1 > r0g) s[ni][1] = -1e30f;
                    if (cb     > r1g) s[ni][2] = -1e30f;
                    if (cb + 1 > r1g) s[ni][3] = -1e30f;
                }
            }
            float mx0 = -1e30f, mx1 = -1e30f;
            #pragma unroll
            for (int ni = 0; ni < 8; ni++) {
                mx0 = fmaxf(mx0, fmaxf(s[ni][0], s[ni][1]));
                mx1 = fmaxf(mx1, fmaxf(s[ni][2], s[ni][3]));
            }
            mx0 = fmaxf(mx0, __shfl_xor_sync(0xffffffffu, mx0, 1));
            mx0 = fmaxf(mx0, __shfl_xor_sync(0xffffffffu, mx0, 2));
            mx1 = fmaxf(mx1, __shfl_xor_sync(0xffffffffu, mx1, 1));
            mx1 = fmaxf(mx1, __shfl_xor_sync(0xffffffffu, mx1, 2));

            float mn0 = fmaxf(m0v, mx0), mn1 = fmaxf(m1v, mx1);
            float ef0 = __expf(m0v - mn0), ef1 = __expf(m1v - mn1);
            m0v = mn0; m1v = mn1;

            float sum0 = 0.f, sum1 = 0.f;
            unsigned p01[8], p23[8];
            #pragma unroll
            for (int ni = 0; ni < 8; ni++) {
                float e0 = __expf(s[ni][0] - mn0);
                float e1 = __expf(s[ni][1] - mn0);
                float e2 = __expf(s[ni][2] - mn1);
                float e3 = __expf(s[ni][3] - mn1);
                sum0 += e0 + e1; sum1 += e2 + e3;
                p01[ni] = ph2(e0, e1);
                p23[ni] = ph2(e2, e3);
            }
            sum0 += __shfl_xor_sync(0xffffffffu, sum0, 1);
            sum0 += __shfl_xor_sync(0xffffffffu, sum0, 2);
            sum1 += __shfl_xor_sync(0xffffffffu, sum1, 1);
            sum1 += __shfl_xor_sync(0xffffffffu, sum1, 2);
            l0 = l0 * ef0 + sum0;
            l1 = l1 * ef1 + sum1;

            #pragma unroll
            for (int ni = 0; ni < 16; ni++) {
                o[ni][0] *= ef0; o[ni][1] *= ef0;
                o[ni][2] *= ef1; o[ni][3] *= ef1;
            }

            // O += P @ V : warp 16 x 128 (16 n-tiles), k=64
            #pragma unroll
            for (int t = 0; t < 4; t++) {
                unsigned ap[4] = { p01[2*t], p23[2*t], p01[2*t + 1], p23[2*t + 1] };
                const int kw = t * 8 + lr;
                #pragma unroll
                for (int ni = 0; ni < 16; ni++) {
                    unsigned bb[2];
                    int nb = ni * 8 + lq;
                    bb[0] = Vs[nb * 36 + kw];
                    bb[1] = Vs[nb * 36 + kw + 4];
                    mma_f16(o[ni], ap, bb);
                }
            }
        }

        // normalize + scatter-write Z into fp16 A-frag panels
        float inv0 = 1.f / l0, inv1 = 1.f / l1;
        const int mglob0 = b * SEQ + q0;     // 128-aligned
        unsigned* Zt = g_Zp + (size_t)(mglob0 >> 7) * PANEL_W;
        const int mrow = r_loc;
        #pragma unroll
        for (int ni = 0; ni < 16; ni++) {
            int e = ni * 8 + 2 * lr;
            int kg = h * DHEAD + e;
            unsigned* Zs = Zt + (size_t)(kg >> 6) * SLAB_W;
            int kl = kg & 63;
            Zs[afrag16(mrow,     kl)] = ph2(o[ni][0] * inv0, o[ni][1] * inv0);
            Zs[afrag16(mrow + 8, kl)] = ph2(o[ni][2] * inv1, o[ni][3] * inv1);
        }
    }
}

// ---------------------------------------------------------------------------
// Phase 3: output projection. grid = (16 n-tiles, 32 m-tiles), 128 threads.
// ---------------------------------------------------------------------------
__global__ __launch_bounds__(128) void out_gemm16(
    const float* __restrict__ bO, float* __restrict__ out)
{
    extern __shared__ __align__(16) unsigned smp[];

    const int n0  = blockIdx.x * 128;
    const int m0  = blockIdx.y * 128;
    const int tid = threadIdx.x;
    const int warp = tid >> 5, lane = tid & 31;
    const int warpM = warp >> 1, warpN = warp & 1;
    const int lq = lane >> 2, lr = lane & 3;

    const unsigned* Ablk0 = g_Zp + (size_t)(m0 >> 7) * PANEL_W;
    const unsigned* Bblk0 = g_WOp + (size_t)(n0 >> 7) * PANEL_W;

    float c[4][8][4];
    #pragma unroll
    for (int mi = 0; mi < 4; mi++)
        #pragma unroll
        for (int ni = 0; ni < 8; ni++)
            #pragma unroll
            for (int j = 0; j < 4; j++) c[mi][ni][j] = 0.f;

    gemm_mainloop64(smp, Ablk0, Bblk0, c, tid, warpM, warpN, lane);

    #pragma unroll
    for (int mi = 0; mi < 4; mi++) {
        #pragma unroll
        for (int half_ = 0; half_ < 2; half_++) {
            int m = m0 + warpM * 64 + mi * 16 + lq + half_ * 8;
            float* orow = out + (size_t)m * DMODEL + n0;
            #pragma unroll
            for (int ni = 0; ni < 8; ni++) {
                int n = warpN * 64 + ni * 8 + 2 * lr;
                float2 r;
                r.x = c[mi][ni][half_ * 2 + 0] + bO[n0 + n];
                r.y = c[mi][ni][half_ * 2 + 1] + bO[n0 + n + 1];
                *(float2*)(orow + n) = r;
            }
        }
    }
}

// ---------------------------------------------------------------------------
extern "C" void kernel_launch(void* const* d_in, const int* in_sizes, int n_in,
                              void* d_out, int out_size)
{
    const float* x  = (const float*)d_in[0];
    const float* Wq = (const float*)d_in[1];
    const float* Wk = (const float*)d_in[2];
    const float* Wv = (const float*)d_in[3];
    const float* Wo = (const float*)d_in[4];
    const float* bq = (const float*)d_in[5];
    const float* bk = (const float*)d_in[6];
    const float* bv = (const float*)d_in[7];
    const float* bo = (const float*)d_in[8];
    float* out = (float*)d_out;

    unsigned *pXp, *pWqp, *pWkp, *pWvp, *pWOp;
    cudaGetSymbolAddress((void**)&pXp,  g_Xp);
    cudaGetSymbolAddress((void**)&pWqp, g_Wqp);
    cudaGetSymbolAddress((void**)&pWkp, g_Wkp);
    cudaGetSymbolAddress((void**)&pWvp, g_Wvp);
    cudaGetSymbolAddress((void**)&pWOp, g_WOp);

    const int NXC = 32 * 32 * 1024;
    const int NWC = 16 * 32 * 1024;
    permute_A16<<<(NXC + 255) / 256, 256>>>(x, pXp, NXC);
    permute_B16_all<<<dim3((NWC + 255) / 256, 4), 256>>>(
        Wq, Wk, Wv, Wo, pWqp, pWkp, pWvp, pWOp, NWC);

    cudaFuncSetAttribute(qkv_gemm16, cudaFuncAttributeMaxDynamicSharedMemorySize, GEMM_SMEM_BYTES);
    qkv_gemm16<<<dim3(16, 32, 3), 128, GEMM_SMEM_BYTES>>>(bq, bk, bv);

    cudaFuncSetAttribute(attn16, cudaFuncAttributeMaxDynamicSharedMemorySize, ATT_SMEM_BYTES);
    attn16<<<dim3(8, 32), 256, ATT_SMEM_BYTES>>>();

    cudaFuncSetAttribute(out_gemm16, cudaFuncAttributeMaxDynamicSharedMemorySize, GEMM_SMEM_BYTES);
    out_gemm16<<<dim3(16, 32), 128, GEMM_SMEM_BYTES>>>(bo, out);
}